// round 13
// baseline (speedup 1.0000x reference)
#include <cuda_runtime.h>
#include <math.h>

#define F 39
#define E 16
#define A 16
#define NPAIR 741            // F*(F-1)/2
#define ESTR 20              // emb row stride: 80 B = odd # of 16B units -> float4-clean
#define WARPS 8
#define THREADS 256

// dynamic smem layout (bytes)
#define OFF_PIJ   0
#define OFF_EMB   1504                          // 1482 rounded to 16B
#define EMB_BYTES (F * ESTR * 4)                // 3120 per warp
#define OFF_SCORE (OFF_EMB + WARPS * EMB_BYTES) // 26464
#define SCORE_BYTES (NPAIR * 4)                 // 2964 per warp
#define SMEM_TOTAL (OFF_SCORE + WARPS * SCORE_BYTES)  // 50176 B

// MLP constants: warp-uniform, compile-time offsets -> uniform const-port
__constant__ __align__(16) float c_W[E * A];
__constant__ __align__(16) float c_ab[A];
__constant__ __align__(16) float c_h[A];
__constant__ __align__(16) float c_pp[E];

// packed fp32x2 FMA (sm_100+; ptxas only emits FFMA2 via this PTX form)
#define FMA2(d, a, b, c) \
    asm("fma.rn.f32x2 %0, %1, %2, %3;" : "=l"(d) : "l"(a), "l"(b), "l"(c))

__global__ __launch_bounds__(THREADS, 2) void afm_kernel(
    const int*   __restrict__ feat_index,   // [B,F]
    const float* __restrict__ feat_value,   // [B,F]
    const float* __restrict__ fow,          // [V,1]
    const float* __restrict__ emb_table,    // [V,E]
    const float* __restrict__ bias,         // [1]
    float*       __restrict__ out,          // [B]
    int nb)
{
    extern __shared__ __align__(16) char dynsmem[];
    unsigned short* s_pij = (unsigned short*)(dynsmem + OFF_PIJ);

    const int tid  = threadIdx.x;
    const int lane = tid & 31;
    const int wid  = tid >> 5;

    // ---- one-time CTA-wide pair table (row-independent) ----
    for (int p = tid; p < NPAIR; p += THREADS) {
        int i = (int)floorf((77.0f - sqrtf(5929.0f - 8.0f * (float)p)) * 0.5f);
        if (i < 0) i = 0;
        if (i > F - 2) i = F - 2;
        while (i < F - 2 && (77 * (i + 1) - (i + 1) * (i + 1)) / 2 <= p) ++i;
        while (i > 0 && (77 * i - i * i) / 2 > p) --i;
        int j = i + 1 + (p - (77 * i - i * i) / 2);
        s_pij[p] = (unsigned short)(i | (j << 8));
    }
    __syncthreads();   // the ONLY block-wide barrier

    const int row = blockIdx.x * WARPS + wid;
    if (row >= nb) return;

    float* emb   = (float*)(dynsmem + OFF_EMB   + wid * EMB_BYTES);
    float* score = (float*)(dynsmem + OFF_SCORE + wid * SCORE_BYTES);
    // temp aliases inside this warp's score region (dead before scores are written)
    int*   t_idx = (int*)score;          // [0,39)
    float* t_val = score + 64;           // [64,103)

    // ---- Phase A: indices, values, first-order, gather ----
    t_idx[lane] = feat_index[row * F + lane];
    t_val[lane] = feat_value[row * F + lane];
    if (lane < F - 32) {
        t_idx[32 + lane] = feat_index[row * F + 32 + lane];
        t_val[32 + lane] = feat_value[row * F + 32 + lane];
    }
    __syncwarp();

    float fo = t_val[lane] * fow[t_idx[lane]];
    if (lane < F - 32) fo += t_val[32 + lane] * fow[t_idx[32 + lane]];

    for (int t = lane; t < F * E; t += 32) {
        int f = t >> 4, e = t & 15;
        emb[f * ESTR + e] = emb_table[t_idx[f] * E + e] * t_val[f];
    }
    __syncwarp();   // all temp reads done; emb visible

    #pragma unroll
    for (int o = 16; o > 0; o >>= 1) fo += __shfl_xor_sync(~0u, fo, o);

    // ---- Phase B: 2 pairs/thread; W LDCU amortized across both ----
    const unsigned long long* ab2 = (const unsigned long long*)c_ab;

    float mloc = -1e30f;
    #pragma unroll 1
    for (int it = 0; it < 12; ++it) {
        int  p0   = it * 64 + lane;          // always < 741 (max 735)
        int  p1   = p0 + 32;
        bool act1 = p1 < NPAIR;
        int  v0   = s_pij[p0];
        int  v1   = s_pij[act1 ? p1 : 0];
        const float4* ei0 = (const float4*)(emb + (v0 & 255) * ESTR);
        const float4* ej0 = (const float4*)(emb + (v0 >> 8) * ESTR);
        const float4* ei1 = (const float4*)(emb + (v1 & 255) * ESTR);
        const float4* ej1 = (const float4*)(emb + (v1 >> 8) * ESTR);

        unsigned long long att0[8], att1[8];
        #pragma unroll
        for (int k = 0; k < 8; ++k) { att0[k] = ab2[k]; att1[k] = ab2[k]; }

        #pragma unroll
        for (int q = 0; q < 4; ++q) {
            float4 a0 = ei0[q], b0 = ej0[q];
            float4 a1 = ei1[q], b1 = ej1[q];
            float bes0[4], bes1[4];
            bes0[0] = a0.x * b0.x;  bes0[1] = a0.y * b0.y;
            bes0[2] = a0.z * b0.z;  bes0[3] = a0.w * b0.w;
            bes1[0] = a1.x * b1.x;  bes1[1] = a1.y * b1.y;
            bes1[2] = a1.z * b1.z;  bes1[3] = a1.w * b1.w;
            #pragma unroll
            for (int s = 0; s < 4; ++s) {
                const int e = 4 * q + s;
                unsigned long long be0, be1;
                asm("mov.b64 %0, {%1, %1};" : "=l"(be0) : "f"(bes0[s]));
                asm("mov.b64 %0, {%1, %1};" : "=l"(be1) : "f"(bes1[s]));
                const ulonglong2* w = (const ulonglong2*)(c_W + e * A);
                ulonglong2 w01 = w[0], w23 = w[1], w45 = w[2], w67 = w[3];
                FMA2(att0[0], be0, w01.x, att0[0]);
                FMA2(att0[1], be0, w01.y, att0[1]);
                FMA2(att0[2], be0, w23.x, att0[2]);
                FMA2(att0[3], be0, w23.y, att0[3]);
                FMA2(att0[4], be0, w45.x, att0[4]);
                FMA2(att0[5], be0, w45.y, att0[5]);
                FMA2(att0[6], be0, w67.x, att0[6]);
                FMA2(att0[7], be0, w67.y, att0[7]);
                FMA2(att1[0], be1, w01.x, att1[0]);
                FMA2(att1[1], be1, w01.y, att1[1]);
                FMA2(att1[2], be1, w23.x, att1[2]);
                FMA2(att1[3], be1, w23.y, att1[3]);
                FMA2(att1[4], be1, w45.x, att1[4]);
                FMA2(att1[5], be1, w45.y, att1[5]);
                FMA2(att1[6], be1, w67.x, att1[6]);
                FMA2(att1[7], be1, w67.y, att1[7]);
            }
        }

        // scalar relu + projection epilogue (proven form)
        float sc0 = 0.0f, sc1 = 0.0f;
        #pragma unroll
        for (int k = 0; k < 8; ++k) {
            float l0, h0, l1, h1;
            asm("mov.b64 {%0, %1}, %2;" : "=f"(l0), "=f"(h0) : "l"(att0[k]));
            asm("mov.b64 {%0, %1}, %2;" : "=f"(l1), "=f"(h1) : "l"(att1[k]));
            sc0 = fmaf(fmaxf(l0, 0.0f), c_h[2 * k],     sc0);
            sc0 = fmaf(fmaxf(h0, 0.0f), c_h[2 * k + 1], sc0);
            sc1 = fmaf(fmaxf(l1, 0.0f), c_h[2 * k],     sc1);
            sc1 = fmaf(fmaxf(h1, 0.0f), c_h[2 * k + 1], sc1);
        }

        score[p0] = sc0;
        mloc = fmaxf(mloc, sc0);
        if (act1) { score[p1] = sc1; mloc = fmaxf(mloc, sc1); }
    }

    // ---- Phase C: warp softmax over 741 pairs ----
    #pragma unroll
    for (int o = 16; o > 0; o >>= 1) mloc = fmaxf(mloc, __shfl_xor_sync(~0u, mloc, o));

    float z = 0.0f;
    #pragma unroll 1
    for (int it = 0; it < 24; ++it) {
        int p = it * 32 + lane;
        if (p < NPAIR) {
            float ev = __expf(score[p] - mloc);
            score[p] = ev;
            z += ev;
        }
    }
    __syncwarp();
    #pragma unroll
    for (int o = 16; o > 0; o >>= 1) z += __shfl_xor_sync(~0u, z, o);

    // ---- Phase D: weighted pooled sum, projection, sigmoid ----
    {
        const int e = lane & 15;
        const int g = lane >> 4;     // 2 pair-groups
        float acc = 0.0f;
        #pragma unroll 2
        for (int p = g; p < NPAIR; p += 2) {
            int v = s_pij[p];
            acc = fmaf(score[p],
                       emb[(v & 255) * ESTR + e] * emb[(v >> 8) * ESTR + e],
                       acc);
        }
        acc += __shfl_xor_sync(~0u, acc, 16);
        float aw = acc * c_pp[e];
        #pragma unroll
        for (int o = 8; o > 0; o >>= 1) aw += __shfl_xor_sync(~0u, aw, o);

        if (lane == 0) {
            float y = bias[0] + fo + aw / z;
            out[row] = 1.0f / (1.0f + __expf(-y));
        }
    }
}

extern "C" void kernel_launch(void* const* d_in, const int* in_sizes, int n_in,
                              void* d_out, int out_size) {
    const int*   feat_index = (const int*)  d_in[0];
    const float* feat_value = (const float*)d_in[1];
    const float* fow        = (const float*)d_in[2];
    const float* emb_table  = (const float*)d_in[3];
    const float* bias       = (const float*)d_in[4];
    float* out = (float*)d_out;

    // Stage the tiny MLP weights into constant memory (graph-capturable
    // device-to-device async copies; no allocation).
    cudaMemcpyToSymbolAsync(c_W,  d_in[5], E * A * sizeof(float), 0, cudaMemcpyDeviceToDevice);
    cudaMemcpyToSymbolAsync(c_ab, d_in[6], A * sizeof(float),     0, cudaMemcpyDeviceToDevice);
    cudaMemcpyToSymbolAsync(c_h,  d_in[7], A * sizeof(float),     0, cudaMemcpyDeviceToDevice);
    cudaMemcpyToSymbolAsync(c_pp, d_in[8], E * sizeof(float),     0, cudaMemcpyDeviceToDevice);

    // Opt in to >48KB dynamic smem (host-side attribute; capture-safe, no alloc).
    cudaFuncSetAttribute(afm_kernel, cudaFuncAttributeMaxDynamicSharedMemorySize,
                         SMEM_TOTAL);

    int nb = in_sizes[0] / F;   // batch rows
    int blocks = (nb + WARPS - 1) / WARPS;
    afm_kernel<<<blocks, THREADS, SMEM_TOTAL>>>(feat_index, feat_value, fow,
                                                emb_table, bias, out, nb);
}

// round 14
// speedup vs baseline: 2.2344x; 2.2344x over previous
#include <cuda_runtime.h>
#include <math.h>

#define F 39
#define E 16
#define A 16
#define NPAIR 741            // F*(F-1)/2
#define ESTR 20              // emb row stride: 80 B = odd # of 16B units -> float4-clean
#define WARPS 8
#define THREADS 256

// dynamic smem layout (bytes)
#define OFF_PIJ   0
#define OFF_EMB   1504                          // 1482 rounded to 16B
#define EMB_BYTES (F * ESTR * 4)                // 3120 per warp
#define OFF_SCORE (OFF_EMB + WARPS * EMB_BYTES) // 26464
#define SCORE_BYTES (NPAIR * 4)                 // 2964 per warp
#define SMEM_TOTAL (OFF_SCORE + WARPS * SCORE_BYTES)  // 50176 B

// MLP constants: warp-uniform, compile-time offsets -> uniform const-port
__constant__ __align__(16) float c_W[E * A];
__constant__ __align__(16) float c_ab[A];
__constant__ __align__(16) float c_h[A];
__constant__ __align__(16) float c_pp[E];

// packed fp32x2 FMA (sm_100+; ptxas only emits FFMA2 via this PTX form)
#define FMA2(d, a, b, c) \
    asm("fma.rn.f32x2 %0, %1, %2, %3;" : "=l"(d) : "l"(a), "l"(b), "l"(c))

__global__ __launch_bounds__(THREADS, 3) void afm_kernel(
    const int*   __restrict__ feat_index,   // [B,F]
    const float* __restrict__ feat_value,   // [B,F]
    const float* __restrict__ fow,          // [V,1]
    const float* __restrict__ emb_table,    // [V,E]
    const float* __restrict__ bias,         // [1]
    float*       __restrict__ out,          // [B]
    int nb)
{
    extern __shared__ __align__(16) char dynsmem[];
    unsigned short* s_pij = (unsigned short*)(dynsmem + OFF_PIJ);

    const int tid  = threadIdx.x;
    const int lane = tid & 31;
    const int wid  = tid >> 5;

    // ---- one-time CTA-wide pair table (row-independent) ----
    for (int p = tid; p < NPAIR; p += THREADS) {
        int i = (int)floorf((77.0f - sqrtf(5929.0f - 8.0f * (float)p)) * 0.5f);
        if (i < 0) i = 0;
        if (i > F - 2) i = F - 2;
        while (i < F - 2 && (77 * (i + 1) - (i + 1) * (i + 1)) / 2 <= p) ++i;
        while (i > 0 && (77 * i - i * i) / 2 > p) --i;
        int j = i + 1 + (p - (77 * i - i * i) / 2);
        s_pij[p] = (unsigned short)(i | (j << 8));
    }
    __syncthreads();   // the ONLY block-wide barrier

    const int row = blockIdx.x * WARPS + wid;
    if (row >= nb) return;

    float* emb   = (float*)(dynsmem + OFF_EMB   + wid * EMB_BYTES);
    float* score = (float*)(dynsmem + OFF_SCORE + wid * SCORE_BYTES);
    // temp aliases inside this warp's score region (dead before scores are written)
    int*   t_idx = (int*)score;          // [0,39)
    float* t_val = score + 64;           // [64,103)

    // ---- Phase A: indices, values, first-order, gather ----
    t_idx[lane] = feat_index[row * F + lane];
    t_val[lane] = feat_value[row * F + lane];
    if (lane < F - 32) {
        t_idx[32 + lane] = feat_index[row * F + 32 + lane];
        t_val[32 + lane] = feat_value[row * F + 32 + lane];
    }
    __syncwarp();

    float fo = t_val[lane] * fow[t_idx[lane]];
    if (lane < F - 32) fo += t_val[32 + lane] * fow[t_idx[32 + lane]];

    for (int t = lane; t < F * E; t += 32) {
        int f = t >> 4, e = t & 15;
        emb[f * ESTR + e] = emb_table[t_idx[f] * E + e] * t_val[f];
    }
    __syncwarp();   // all temp reads done; emb visible

    #pragma unroll
    for (int o = 16; o > 0; o >>= 1) fo += __shfl_xor_sync(~0u, fo, o);

    // ---- Phase B: pair scores (float4 emb loads, LDCU.128 W, packed MLP) ----
    float mloc = -1e30f;
    #pragma unroll 1
    for (int it = 0; it < 24; ++it) {
        int  p   = it * 32 + lane;
        bool act = p < NPAIR;
        int  v   = s_pij[act ? p : 0];
        const float4* ei4 = (const float4*)(emb + (v & 255) * ESTR);
        const float4* ej4 = (const float4*)(emb + (v >> 8) * ESTR);

        unsigned long long att[8];
        #pragma unroll
        for (int k = 0; k < 8; ++k)
            att[k] = ((const unsigned long long*)c_ab)[k];

        #pragma unroll
        for (int q = 0; q < 4; ++q) {
            float4 va = ei4[q];
            float4 vb = ej4[q];
            float bes[4];
            bes[0] = va.x * vb.x;
            bes[1] = va.y * vb.y;
            bes[2] = va.z * vb.z;
            bes[3] = va.w * vb.w;
            #pragma unroll
            for (int s = 0; s < 4; ++s) {
                const int e = 4 * q + s;
                unsigned long long be2;
                asm("mov.b64 %0, {%1, %1};" : "=l"(be2) : "f"(bes[s]));
                const ulonglong2* w = (const ulonglong2*)(c_W + e * A);
                ulonglong2 w01 = w[0], w23 = w[1], w45 = w[2], w67 = w[3];
                FMA2(att[0], be2, w01.x, att[0]);
                FMA2(att[1], be2, w01.y, att[1]);
                FMA2(att[2], be2, w23.x, att[2]);
                FMA2(att[3], be2, w23.y, att[3]);
                FMA2(att[4], be2, w45.x, att[4]);
                FMA2(att[5], be2, w45.y, att[5]);
                FMA2(att[6], be2, w67.x, att[6]);
                FMA2(att[7], be2, w67.y, att[7]);
            }
        }

        float sc = 0.0f;
        #pragma unroll
        for (int k = 0; k < 8; ++k) {
            float lo, hi;
            asm("mov.b64 {%0, %1}, %2;" : "=f"(lo), "=f"(hi) : "l"(att[k]));
            sc = fmaf(fmaxf(lo, 0.0f), c_h[2 * k],     sc);
            sc = fmaf(fmaxf(hi, 0.0f), c_h[2 * k + 1], sc);
        }
        if (act) { score[p] = sc; mloc = fmaxf(mloc, sc); }
    }

    // ---- Phase C: warp softmax over 741 pairs ----
    #pragma unroll
    for (int o = 16; o > 0; o >>= 1) mloc = fmaxf(mloc, __shfl_xor_sync(~0u, mloc, o));

    float z = 0.0f;
    #pragma unroll 1
    for (int it = 0; it < 24; ++it) {
        int p = it * 32 + lane;
        if (p < NPAIR) {
            float ev = __expf(score[p] - mloc);
            score[p] = ev;
            z += ev;
        }
    }
    __syncwarp();
    #pragma unroll
    for (int o = 16; o > 0; o >>= 1) z += __shfl_xor_sync(~0u, z, o);

    // ---- Phase D: weighted pooled sum (float4 over e-quads), projection ----
    {
        const int eq = lane & 3;     // e-quad: e = 4*eq .. 4*eq+3
        const int g  = lane >> 2;    // 8 pair-groups
        float4 acc = make_float4(0.f, 0.f, 0.f, 0.f);
        #pragma unroll 2
        for (int p = g; p < NPAIR; p += 8) {
            int v = s_pij[p];
            float  s  = score[p];                       // broadcast across the 4 eq lanes
            float4 a4 = ((const float4*)(emb + (v & 255) * ESTR))[eq];
            float4 b4 = ((const float4*)(emb + (v >> 8) * ESTR))[eq];
            acc.x = fmaf(s, a4.x * b4.x, acc.x);
            acc.y = fmaf(s, a4.y * b4.y, acc.y);
            acc.z = fmaf(s, a4.z * b4.z, acc.z);
            acc.w = fmaf(s, a4.w * b4.w, acc.w);
        }
        // reduce across the 8 pair-groups (lanes with same eq)
        #pragma unroll
        for (int o = 4; o <= 16; o <<= 1) {
            acc.x += __shfl_xor_sync(~0u, acc.x, o);
            acc.y += __shfl_xor_sync(~0u, acc.y, o);
            acc.z += __shfl_xor_sync(~0u, acc.z, o);
            acc.w += __shfl_xor_sync(~0u, acc.w, o);
        }
        // dot with projection_p quad, then reduce across the 4 eq lanes
        const float4 pp = ((const float4*)c_pp)[eq];
        float aw = acc.x * pp.x + acc.y * pp.y + acc.z * pp.z + acc.w * pp.w;
        aw += __shfl_xor_sync(~0u, aw, 1);
        aw += __shfl_xor_sync(~0u, aw, 2);

        if (lane == 0) {
            float y = bias[0] + fo + aw / z;
            out[row] = 1.0f / (1.0f + __expf(-y));
        }
    }
}

extern "C" void kernel_launch(void* const* d_in, const int* in_sizes, int n_in,
                              void* d_out, int out_size) {
    const int*   feat_index = (const int*)  d_in[0];
    const float* feat_value = (const float*)d_in[1];
    const float* fow        = (const float*)d_in[2];
    const float* emb_table  = (const float*)d_in[3];
    const float* bias       = (const float*)d_in[4];
    float* out = (float*)d_out;

    // Stage the tiny MLP weights into constant memory (graph-capturable
    // device-to-device async copies; no allocation).
    cudaMemcpyToSymbolAsync(c_W,  d_in[5], E * A * sizeof(float), 0, cudaMemcpyDeviceToDevice);
    cudaMemcpyToSymbolAsync(c_ab, d_in[6], A * sizeof(float),     0, cudaMemcpyDeviceToDevice);
    cudaMemcpyToSymbolAsync(c_h,  d_in[7], A * sizeof(float),     0, cudaMemcpyDeviceToDevice);
    cudaMemcpyToSymbolAsync(c_pp, d_in[8], E * sizeof(float),     0, cudaMemcpyDeviceToDevice);

    // Opt in to >48KB dynamic smem (host-side attribute; capture-safe, no alloc).
    cudaFuncSetAttribute(afm_kernel, cudaFuncAttributeMaxDynamicSharedMemorySize,
                         SMEM_TOTAL);

    int nb = in_sizes[0] / F;   // batch rows
    int blocks = (nb + WARPS - 1) / WARPS;
    afm_kernel<<<blocks, THREADS, SMEM_TOTAL>>>(feat_index, feat_value, fow,
                                                emb_table, bias, out, nb);
}

// round 15
// speedup vs baseline: 2.3910x; 1.0701x over previous
#include <cuda_runtime.h>
#include <math.h>

#define F 39
#define E 16
#define A 16
#define NPAIR 741            // F*(F-1)/2
#define ESTR 20              // emb row stride: 80 B = odd # of 16B units -> float4-clean
#define WARPS 8
#define THREADS 256

// dynamic smem layout (bytes)
#define OFF_PIJ   0
#define EMB_BYTES (F * ESTR * 4 + 320)          // 3120 emb + 320 temp tail = 3440
#define OFF_EMB   1504                          // 1482 rounded to 16B
#define SMEM_TOTAL (OFF_EMB + WARPS * EMB_BYTES)  // 29024 B

// MLP constants: warp-uniform, compile-time offsets -> uniform const-port
__constant__ __align__(16) float c_W[E * A];
__constant__ __align__(16) float c_ab[A];
__constant__ __align__(16) float c_h[A];
__constant__ __align__(16) float c_pp[E];

// packed fp32x2 ops (sm_100+; only fma/mul/add exist — max.f32x2 does NOT)
#define FMA2(d, a, b, c) \
    asm("fma.rn.f32x2 %0, %1, %2, %3;" : "=l"(d) : "l"(a), "l"(b), "l"(c))
#define MUL2(d, a, b) \
    asm("mul.rn.f32x2 %0, %1, %2;" : "=l"(d) : "l"(a), "l"(b))
#define PACK2(d, lo, hi) \
    asm("mov.b64 %0, {%1, %2};" : "=l"(d) : "f"(lo), "f"(hi))
#define BCAST2(d, x) \
    asm("mov.b64 %0, {%1, %1};" : "=l"(d) : "f"(x))
#define UNPACK2(lo, hi, s) \
    asm("mov.b64 {%0, %1}, %2;" : "=f"(lo), "=f"(hi) : "l"(s))

__global__ __launch_bounds__(THREADS, 3) void afm_kernel(
    const int*   __restrict__ feat_index,   // [B,F]
    const float* __restrict__ feat_value,   // [B,F]
    const float* __restrict__ fow,          // [V,1]
    const float* __restrict__ emb_table,    // [V,E]
    const float* __restrict__ bias,         // [1]
    float*       __restrict__ out,          // [B]
    int nb)
{
    extern __shared__ __align__(16) char dynsmem[];
    unsigned short* s_pij = (unsigned short*)(dynsmem + OFF_PIJ);

    const int tid  = threadIdx.x;
    const int lane = tid & 31;
    const int wid  = tid >> 5;

    // ---- one-time CTA-wide pair table (row-independent) ----
    for (int p = tid; p < NPAIR; p += THREADS) {
        int i = (int)floorf((77.0f - sqrtf(5929.0f - 8.0f * (float)p)) * 0.5f);
        if (i < 0) i = 0;
        if (i > F - 2) i = F - 2;
        while (i < F - 2 && (77 * (i + 1) - (i + 1) * (i + 1)) / 2 <= p) ++i;
        while (i > 0 && (77 * i - i * i) / 2 > p) --i;
        int j = i + 1 + (p - (77 * i - i * i) / 2);
        s_pij[p] = (unsigned short)(i | (j << 8));
    }
    __syncthreads();   // the ONLY block-wide barrier

    const int row = blockIdx.x * WARPS + wid;
    if (row >= nb) return;

    float* emb   = (float*)(dynsmem + OFF_EMB + wid * EMB_BYTES);
    // temps live in the tail of this warp's emb region (disjoint from emb data)
    int*   t_idx = (int*)(dynsmem + OFF_EMB + wid * EMB_BYTES + F * ESTR * 4);
    float* t_val = (float*)(t_idx + 40);

    // ---- Phase A: indices, values, first-order, gather ----
    t_idx[lane] = feat_index[row * F + lane];
    t_val[lane] = feat_value[row * F + lane];
    if (lane < F - 32) {
        t_idx[32 + lane] = feat_index[row * F + 32 + lane];
        t_val[32 + lane] = feat_value[row * F + 32 + lane];
    }
    __syncwarp();

    float fo = t_val[lane] * fow[t_idx[lane]];
    if (lane < F - 32) fo += t_val[32 + lane] * fow[t_idx[32 + lane]];

    for (int t = lane; t < F * E; t += 32) {
        int f = t >> 4, e = t & 15;
        emb[f * ESTR + e] = emb_table[t_idx[f] * E + e] * t_val[f];
    }
    __syncwarp();

    #pragma unroll
    for (int o = 16; o > 0; o >>= 1) fo += __shfl_xor_sync(~0u, fo, o);

    // ---- Phase B: fused pair scores + ONLINE softmax + weighted pooling ----
    // Per-lane streaming state: running max m, normalizer z, acc[e] (packed pairs).
    float m = -1e30f;
    float z = 0.0f;
    unsigned long long acc[8];
    #pragma unroll
    for (int k = 0; k < 8; ++k) acc[k] = 0ull;

    #pragma unroll 1
    for (int it = 0; it < 24; ++it) {
        int  p   = it * 32 + lane;
        bool act = p < NPAIR;
        int  v   = s_pij[act ? p : 0];
        const float4* ei4 = (const float4*)(emb + (v & 255) * ESTR);
        const float4* ej4 = (const float4*)(emb + (v >> 8) * ESTR);

        unsigned long long att[8];
        #pragma unroll
        for (int k = 0; k < 8; ++k)
            att[k] = ((const unsigned long long*)c_ab)[k];

        unsigned long long be2p[8];   // bi packed as {e,e+1} pairs, kept for pooling
        #pragma unroll
        for (int q = 0; q < 4; ++q) {
            float4 va = ei4[q];
            float4 vb = ej4[q];
            float bes[4];
            bes[0] = va.x * vb.x;
            bes[1] = va.y * vb.y;
            bes[2] = va.z * vb.z;
            bes[3] = va.w * vb.w;
            PACK2(be2p[2 * q],     bes[0], bes[1]);
            PACK2(be2p[2 * q + 1], bes[2], bes[3]);
            #pragma unroll
            for (int s = 0; s < 4; ++s) {
                const int e = 4 * q + s;
                unsigned long long be2;
                BCAST2(be2, bes[s]);
                const ulonglong2* w = (const ulonglong2*)(c_W + e * A);
                ulonglong2 w01 = w[0], w23 = w[1], w45 = w[2], w67 = w[3];
                FMA2(att[0], be2, w01.x, att[0]);
                FMA2(att[1], be2, w01.y, att[1]);
                FMA2(att[2], be2, w23.x, att[2]);
                FMA2(att[3], be2, w23.y, att[3]);
                FMA2(att[4], be2, w45.x, att[4]);
                FMA2(att[5], be2, w45.y, att[5]);
                FMA2(att[6], be2, w67.x, att[6]);
                FMA2(att[7], be2, w67.y, att[7]);
            }
        }

        float sc = 0.0f;
        #pragma unroll
        for (int k = 0; k < 8; ++k) {
            float lo, hi;
            UNPACK2(lo, hi, att[k]);
            sc = fmaf(fmaxf(lo, 0.0f), c_h[2 * k],     sc);
            sc = fmaf(fmaxf(hi, 0.0f), c_h[2 * k + 1], sc);
        }

        if (act) {
            if (sc > m) {                 // rare: rescale history to new max
                float c = __expf(m - sc);
                m = sc;
                z *= c;
                unsigned long long c2;
                BCAST2(c2, c);
                #pragma unroll
                for (int k = 0; k < 8; ++k) MUL2(acc[k], acc[k], c2);
            }
            float pw = __expf(sc - m);
            z += pw;
            unsigned long long p2;
            BCAST2(p2, pw);
            #pragma unroll
            for (int k = 0; k < 8; ++k) FMA2(acc[k], p2, be2p[k], acc[k]);
        }
    }

    // ---- cross-lane merge of (m, z, acc) with rescaling ----
    #pragma unroll
    for (int o = 16; o > 0; o >>= 1) {
        float m_o = __shfl_xor_sync(~0u, m, o);
        float z_o = __shfl_xor_sync(~0u, z, o);
        unsigned long long acc_o[8];
        #pragma unroll
        for (int k = 0; k < 8; ++k)
            acc_o[k] = __shfl_xor_sync(~0u, acc[k], o);
        float mn = fmaxf(m, m_o);
        float cs = __expf(m - mn);
        float co = __expf(m_o - mn);
        z = z * cs + z_o * co;
        unsigned long long cs2, co2;
        BCAST2(cs2, cs);
        BCAST2(co2, co);
        #pragma unroll
        for (int k = 0; k < 8; ++k) {
            unsigned long long t;
            MUL2(t, acc[k], cs2);
            FMA2(acc[k], acc_o[k], co2, t);
        }
        m = mn;
    }

    // ---- projection + sigmoid (all lanes hold identical totals) ----
    if (lane == 0) {
        unsigned long long s2 = 0ull;
        const unsigned long long* pp2 = (const unsigned long long*)c_pp;
        #pragma unroll
        for (int k = 0; k < 8; ++k) FMA2(s2, acc[k], pp2[k], s2);
        float lo, hi;
        UNPACK2(lo, hi, s2);
        float aw = lo + hi;
        float y = bias[0] + fo + aw / z;
        out[row] = 1.0f / (1.0f + __expf(-y));
    }
}

extern "C" void kernel_launch(void* const* d_in, const int* in_sizes, int n_in,
                              void* d_out, int out_size) {
    const int*   feat_index = (const int*)  d_in[0];
    const float* feat_value = (const float*)d_in[1];
    const float* fow        = (const float*)d_in[2];
    const float* emb_table  = (const float*)d_in[3];
    const float* bias       = (const float*)d_in[4];
    float* out = (float*)d_out;

    // Stage the tiny MLP weights into constant memory (graph-capturable
    // device-to-device async copies; no allocation).
    cudaMemcpyToSymbolAsync(c_W,  d_in[5], E * A * sizeof(float), 0, cudaMemcpyDeviceToDevice);
    cudaMemcpyToSymbolAsync(c_ab, d_in[6], A * sizeof(float),     0, cudaMemcpyDeviceToDevice);
    cudaMemcpyToSymbolAsync(c_h,  d_in[7], A * sizeof(float),     0, cudaMemcpyDeviceToDevice);
    cudaMemcpyToSymbolAsync(c_pp, d_in[8], E * sizeof(float),     0, cudaMemcpyDeviceToDevice);

    cudaFuncSetAttribute(afm_kernel, cudaFuncAttributeMaxDynamicSharedMemorySize,
                         SMEM_TOTAL);

    int nb = in_sizes[0] / F;   // batch rows
    int blocks = (nb + WARPS - 1) / WARPS;
    afm_kernel<<<blocks, THREADS, SMEM_TOTAL>>>(feat_index, feat_value, fow,
                                                emb_table, bias, out, nb);
}

// round 16
// speedup vs baseline: 2.3988x; 1.0033x over previous
#include <cuda_runtime.h>
#include <math.h>

#define F 39
#define E 16
#define A 16
#define NPAIR 741            // F*(F-1)/2
#define ESTR 20              // emb row stride: 80 B = odd # of 16B units -> float4-clean
#define WARPS 8
#define THREADS 256

// dynamic smem layout (bytes)
#define OFF_PIJ   0
#define EMB_BYTES (F * ESTR * 4 + 320)          // 3120 emb + 320 temp tail = 3440
#define OFF_EMB   1504                          // 1482 rounded to 16B
#define SMEM_TOTAL (OFF_EMB + WARPS * EMB_BYTES)  // 29024 B

// MLP constants: warp-uniform, compile-time offsets -> uniform const-port
__constant__ __align__(16) float c_W[E * A];
__constant__ __align__(16) float c_ab[A];
__constant__ __align__(16) float c_h[A];
__constant__ __align__(16) float c_pp[E];

// packed fp32x2 ops (sm_100+; only fma/mul/add exist — max.f32x2 does NOT)
#define FMA2(d, a, b, c) \
    asm("fma.rn.f32x2 %0, %1, %2, %3;" : "=l"(d) : "l"(a), "l"(b), "l"(c))
#define MUL2(d, a, b) \
    asm("mul.rn.f32x2 %0, %1, %2;" : "=l"(d) : "l"(a), "l"(b))
#define PACK2(d, lo, hi) \
    asm("mov.b64 %0, {%1, %2};" : "=l"(d) : "f"(lo), "f"(hi))
#define BCAST2(d, x) \
    asm("mov.b64 %0, {%1, %1};" : "=l"(d) : "f"(x))
#define UNPACK2(lo, hi, s) \
    asm("mov.b64 {%0, %1}, %2;" : "=f"(lo), "=f"(hi) : "l"(s))

__global__ __launch_bounds__(THREADS, 4) void afm_kernel(
    const int*   __restrict__ feat_index,   // [B,F]
    const float* __restrict__ feat_value,   // [B,F]
    const float* __restrict__ fow,          // [V,1]
    const float* __restrict__ emb_table,    // [V,E]
    const float* __restrict__ bias,         // [1]
    float*       __restrict__ out,          // [B]
    int nb)
{
    extern __shared__ __align__(16) char dynsmem[];
    unsigned short* s_pij = (unsigned short*)(dynsmem + OFF_PIJ);

    const int tid  = threadIdx.x;
    const int lane = tid & 31;
    const int wid  = tid >> 5;

    // ---- one-time CTA-wide pair table (row-independent) ----
    for (int p = tid; p < NPAIR; p += THREADS) {
        int i = (int)floorf((77.0f - sqrtf(5929.0f - 8.0f * (float)p)) * 0.5f);
        if (i < 0) i = 0;
        if (i > F - 2) i = F - 2;
        while (i < F - 2 && (77 * (i + 1) - (i + 1) * (i + 1)) / 2 <= p) ++i;
        while (i > 0 && (77 * i - i * i) / 2 > p) --i;
        int j = i + 1 + (p - (77 * i - i * i) / 2);
        s_pij[p] = (unsigned short)(i | (j << 8));
    }
    __syncthreads();   // the ONLY block-wide barrier

    const int row = blockIdx.x * WARPS + wid;
    if (row >= nb) return;

    float* emb   = (float*)(dynsmem + OFF_EMB + wid * EMB_BYTES);
    // temps live in the tail of this warp's emb region (disjoint from emb data)
    int*   t_idx = (int*)(dynsmem + OFF_EMB + wid * EMB_BYTES + F * ESTR * 4);
    float* t_val = (float*)(t_idx + 40);

    // ---- Phase A: indices, values, first-order, gather ----
    t_idx[lane] = feat_index[row * F + lane];
    t_val[lane] = feat_value[row * F + lane];
    if (lane < F - 32) {
        t_idx[32 + lane] = feat_index[row * F + 32 + lane];
        t_val[32 + lane] = feat_value[row * F + 32 + lane];
    }
    __syncwarp();

    float fo = t_val[lane] * fow[t_idx[lane]];
    if (lane < F - 32) fo += t_val[32 + lane] * fow[t_idx[32 + lane]];

    for (int t = lane; t < F * E; t += 32) {
        int f = t >> 4, e = t & 15;
        emb[f * ESTR + e] = emb_table[t_idx[f] * E + e] * t_val[f];
    }
    __syncwarp();

    #pragma unroll
    for (int o = 16; o > 0; o >>= 1) fo += __shfl_xor_sync(~0u, fo, o);

    // ---- Phase B: fused pair scores + ONLINE softmax + weighted pooling ----
    // Per-lane streaming state: running max m, normalizer z, acc[e] (packed pairs).
    float m = -1e30f;
    float z = 0.0f;
    unsigned long long acc[8];
    #pragma unroll
    for (int k = 0; k < 8; ++k) acc[k] = 0ull;

    #pragma unroll 1
    for (int it = 0; it < 24; ++it) {
        int  p   = it * 32 + lane;
        bool act = p < NPAIR;
        int  v   = s_pij[act ? p : 0];
        const float4* ei4 = (const float4*)(emb + (v & 255) * ESTR);
        const float4* ej4 = (const float4*)(emb + (v >> 8) * ESTR);

        unsigned long long att[8];
        #pragma unroll
        for (int k = 0; k < 8; ++k)
            att[k] = ((const unsigned long long*)c_ab)[k];

        unsigned long long be2p[8];   // bi packed as {e,e+1} pairs, kept for pooling
        #pragma unroll
        for (int q = 0; q < 4; ++q) {
            float4 va = ei4[q];
            float4 vb = ej4[q];
            float bes[4];
            bes[0] = va.x * vb.x;
            bes[1] = va.y * vb.y;
            bes[2] = va.z * vb.z;
            bes[3] = va.w * vb.w;
            PACK2(be2p[2 * q],     bes[0], bes[1]);
            PACK2(be2p[2 * q + 1], bes[2], bes[3]);
            #pragma unroll
            for (int s = 0; s < 4; ++s) {
                const int e = 4 * q + s;
                unsigned long long be2;
                BCAST2(be2, bes[s]);
                const ulonglong2* w = (const ulonglong2*)(c_W + e * A);
                ulonglong2 w01 = w[0], w23 = w[1], w45 = w[2], w67 = w[3];
                FMA2(att[0], be2, w01.x, att[0]);
                FMA2(att[1], be2, w01.y, att[1]);
                FMA2(att[2], be2, w23.x, att[2]);
                FMA2(att[3], be2, w23.y, att[3]);
                FMA2(att[4], be2, w45.x, att[4]);
                FMA2(att[5], be2, w45.y, att[5]);
                FMA2(att[6], be2, w67.x, att[6]);
                FMA2(att[7], be2, w67.y, att[7]);
            }
        }

        float sc = 0.0f;
        #pragma unroll
        for (int k = 0; k < 8; ++k) {
            float lo, hi;
            UNPACK2(lo, hi, att[k]);
            sc = fmaf(fmaxf(lo, 0.0f), c_h[2 * k],     sc);
            sc = fmaf(fmaxf(hi, 0.0f), c_h[2 * k + 1], sc);
        }

        if (act) {
            if (sc > m) {                 // rare: rescale history to new max
                float c = __expf(m - sc);
                m = sc;
                z *= c;
                unsigned long long c2;
                BCAST2(c2, c);
                #pragma unroll
                for (int k = 0; k < 8; ++k) MUL2(acc[k], acc[k], c2);
            }
            float pw = __expf(sc - m);
            z += pw;
            unsigned long long p2;
            BCAST2(p2, pw);
            #pragma unroll
            for (int k = 0; k < 8; ++k) FMA2(acc[k], p2, be2p[k], acc[k]);
        }
    }

    // ---- cross-lane merge of (m, z, acc) with rescaling ----
    #pragma unroll
    for (int o = 16; o > 0; o >>= 1) {
        float m_o = __shfl_xor_sync(~0u, m, o);
        float z_o = __shfl_xor_sync(~0u, z, o);
        unsigned long long acc_o[8];
        #pragma unroll
        for (int k = 0; k < 8; ++k)
            acc_o[k] = __shfl_xor_sync(~0u, acc[k], o);
        float mn = fmaxf(m, m_o);
        float cs = __expf(m - mn);
        float co = __expf(m_o - mn);
        z = z * cs + z_o * co;
        unsigned long long cs2, co2;
        BCAST2(cs2, cs);
        BCAST2(co2, co);
        #pragma unroll
        for (int k = 0; k < 8; ++k) {
            unsigned long long t;
            MUL2(t, acc[k], cs2);
            FMA2(acc[k], acc_o[k], co2, t);
        }
        m = mn;
    }

    // ---- projection + sigmoid (all lanes hold identical totals) ----
    if (lane == 0) {
        unsigned long long s2 = 0ull;
        const unsigned long long* pp2 = (const unsigned long long*)c_pp;
        #pragma unroll
        for (int k = 0; k < 8; ++k) FMA2(s2, acc[k], pp2[k], s2);
        float lo, hi;
        UNPACK2(lo, hi, s2);
        float aw = lo + hi;
        float y = bias[0] + fo + aw / z;
        out[row] = 1.0f / (1.0f + __expf(-y));
    }
}

extern "C" void kernel_launch(void* const* d_in, const int* in_sizes, int n_in,
                              void* d_out, int out_size) {
    const int*   feat_index = (const int*)  d_in[0];
    const float* feat_value = (const float*)d_in[1];
    const float* fow        = (const float*)d_in[2];
    const float* emb_table  = (const float*)d_in[3];
    const float* bias       = (const float*)d_in[4];
    float* out = (float*)d_out;

    // Stage the tiny MLP weights into constant memory (graph-capturable
    // device-to-device async copies; no allocation).
    cudaMemcpyToSymbolAsync(c_W,  d_in[5], E * A * sizeof(float), 0, cudaMemcpyDeviceToDevice);
    cudaMemcpyToSymbolAsync(c_ab, d_in[6], A * sizeof(float),     0, cudaMemcpyDeviceToDevice);
    cudaMemcpyToSymbolAsync(c_h,  d_in[7], A * sizeof(float),     0, cudaMemcpyDeviceToDevice);
    cudaMemcpyToSymbolAsync(c_pp, d_in[8], E * sizeof(float),     0, cudaMemcpyDeviceToDevice);

    cudaFuncSetAttribute(afm_kernel, cudaFuncAttributeMaxDynamicSharedMemorySize,
                         SMEM_TOTAL);

    int nb = in_sizes[0] / F;   // batch rows
    int blocks = (nb + WARPS - 1) / WARPS;
    afm_kernel<<<blocks, THREADS, SMEM_TOTAL>>>(feat_index, feat_value, fow,
                                                emb_table, bias, out, nb);
}